// round 5
// baseline (speedup 1.0000x reference)
#include <cuda_runtime.h>
#include <math.h>

#define ULL unsigned long long

// ---------------- scratch (__device__ globals: no allocation allowed) --------
__device__ float g_weff[32 * 800];    // per-batch effective key-projection vector
__device__ float g_cst [32 * 2];      // per-batch {S1, S2+gdot+c0}
__device__ float g_scores[32 * 1024]; // pre-softmax scores (cls row excluded)

// ---------------- f32x2 packed-FMA helpers (sm_100+) ------------------------
__device__ __forceinline__ ULL bcast2(float a) {
    ULL r; asm("mov.b64 %0, {%1, %1};" : "=l"(r) : "f"(a)); return r;
}
__device__ __forceinline__ void fma2(ULL &d, ULL a, ULL b) {
    asm("fma.rn.f32x2 %0, %1, %2, %0;" : "+l"(d) : "l"(a), "l"(b));
}
__device__ __forceinline__ float2 unpk(ULL v) {
    float2 f; asm("mov.b64 {%0, %1}, %2;" : "=f"(f.x), "=f"(f.y) : "l"(v)); return f;
}

// ============================================================================
// Kernel 1: per-batch prep.
//   q_cls[b] = Wq @ t0 + bq       (t0 = [cls_token(768), gender(32)])
//   w_eff[b,e] = sum_d q_cls[d] * Wk[d,e]
//   S1 = sum_{e<768} ln_g[e]*w_eff[e],  S2 = sum ln_b[e]*w_eff[e]
//   gdot = sum_j gender[j]*w_eff[768+j], c0 = q_cls . bk
// One block per batch. ~82 MB of L2-resident weight reads total.
// ============================================================================
__global__ void prep_kernel(const float* __restrict__ gender,
                            const float* __restrict__ cls,
                            const float* __restrict__ qkv_w,
                            const float* __restrict__ qkv_b,
                            const float* __restrict__ ln_g,
                            const float* __restrict__ ln_b)
{
    __shared__ float t0[800];
    __shared__ float q[800];
    __shared__ float red[24];
    const int b = blockIdx.x, tid = threadIdx.x;

    for (int i = tid; i < 800; i += 256)
        t0[i] = (i < 768) ? cls[i] : gender[b * 32 + i - 768];
    __syncthreads();

    // q_cls
    for (int d = tid; d < 800; d += 256) {
        const float* wr = qkv_w + (size_t)d * 800;
        float acc = qkv_b[d];
        #pragma unroll 8
        for (int e = 0; e < 800; e++) acc = fmaf(wr[e], t0[e], acc);
        q[d] = acc;
    }
    __syncthreads();

    // w_eff + partial consts
    float ps1 = 0.f, ps2 = 0.f, pex = 0.f;
    for (int e = tid; e < 800; e += 256) {
        const float* wk = qkv_w + 640000 + e;   // Wk[d][e] = qkv_w[(800+d)*800+e]
        float acc = 0.f;
        #pragma unroll 8
        for (int d = 0; d < 800; d++) acc = fmaf(q[d], wk[(size_t)d * 800], acc);
        g_weff[b * 800 + e] = acc;
        if (e < 768) { ps1 = fmaf(ln_g[e], acc, ps1); ps2 = fmaf(ln_b[e], acc, ps2); }
        else         { pex = fmaf(t0[e],  acc, pex); }   // gender . w_eff
    }
    for (int d = tid; d < 800; d += 256)
        pex = fmaf(q[d], qkv_b[800 + d], pex);           // c0

    #pragma unroll
    for (int off = 16; off; off >>= 1) {
        ps1 += __shfl_xor_sync(0xffffffffu, ps1, off);
        ps2 += __shfl_xor_sync(0xffffffffu, ps2, off);
        pex += __shfl_xor_sync(0xffffffffu, pex, off);
    }
    const int w = tid >> 5;
    if ((tid & 31) == 0) { red[w] = ps1; red[8 + w] = ps2; red[16 + w] = pex; }
    __syncthreads();
    if (tid == 0) {
        float S1 = 0.f, S2 = 0.f, EX = 0.f;
        for (int i = 0; i < 8; i++) { S1 += red[i]; S2 += red[8 + i]; EX += red[16 + i]; }
        g_cst[b * 2 + 0] = S1;
        g_cst[b * 2 + 1] = S2 + EX;
    }
}

// ============================================================================
// Kernel 2: fused conv-GEMM + LN-statistics + score.
//   p[n,e] = sum_c x[b,c,n] * W[e,c] + conv_b[e]        (never materialized)
//   per token: s1 = sum_e p, s2 = sum_e p^2, sd = sum_e p * ln_g[e]*w_eff[b,e]
//   score = scale * (rstd*(sd - mu*S1) + K2)
// CTA: 128 tokens x 128 embeds per E-pass, 6 passes, K=1024 in chunks of 16.
// 256 threads, warp grid 4(m) x 2(e), lane grid 4(m) x 8(e), thread tile 8x8.
// Inner loop uses packed fma.rn.f32x2 -> 2x fp32 throughput.
// ============================================================================
__global__ __launch_bounds__(256)
void fused_kernel(const float* __restrict__ x,
                  const float* __restrict__ W,
                  const float* __restrict__ conv_b,
                  const float* __restrict__ ln_g)
{
    __shared__ __align__(16) float As[16][128];
    __shared__ __align__(16) float Bs[16][132];   // +4 pad: spreads store banks
    __shared__ float uS[768];
    __shared__ float cbS[768];
    __shared__ float redS[3][128];

    const int tid = threadIdx.x;
    const int b = blockIdx.y;
    const int m0 = blockIdx.x * 128;
    const float* xb = x + (size_t)b * (1024 * 1024);

    for (int i = tid; i < 768; i += 256) {
        uS[i]  = ln_g[i] * g_weff[b * 800 + i];
        cbS[i] = conv_b[i];
    }

    const int w  = tid >> 5, lane = tid & 31;
    const int wm = w & 3,  we  = w >> 2;
    const int lm = lane >> 3, le = lane & 7;
    const int tm  = wm * 32 + lm * 8;   // 8 token rows: tm..tm+7
    const int teL = we * 64 + le * 8;   // 8 embed cols within pass tile

    float r1[8], r2[8], rd[8];
    #pragma unroll
    for (int i = 0; i < 8; i++) { r1[i] = 0.f; r2[i] = 0.f; rd[i] = 0.f; }

    for (int ep = 0; ep < 6; ep++) {
        const int e0 = ep * 128;
        ULL acc[8][4];
        #pragma unroll
        for (int i = 0; i < 8; i++)
            #pragma unroll
            for (int j = 0; j < 4; j++) acc[i][j] = 0ull;

        for (int kc = 0; kc < 64; kc++) {
            __syncthreads();
            const int c0 = kc * 16;
            {
                // A: x[b, c0..c0+15, m0..m0+127] -> As[16][128]   (coalesced f4)
                int f = tid;
                #pragma unroll
                for (int it = 0; it < 2; it++, f += 256) {
                    int r = f >> 5, c4 = (f & 31) * 4;
                    float4 v = *(const float4*)(xb + (size_t)(c0 + r) * 1024 + m0 + c4);
                    *(float4*)&As[r][c4] = v;
                }
                // B: W[e0..e0+127, c0..c0+15] -> Bs[16][128] (transposed store)
                f = tid;
                #pragma unroll
                for (int it = 0; it < 2; it++, f += 256) {
                    int e = f >> 2, qq = (f & 3) * 4;
                    float4 v = *(const float4*)(W + (size_t)(e0 + e) * 1024 + c0 + qq);
                    Bs[qq + 0][e] = v.x; Bs[qq + 1][e] = v.y;
                    Bs[qq + 2][e] = v.z; Bs[qq + 3][e] = v.w;
                }
            }
            __syncthreads();
            #pragma unroll
            for (int kk = 0; kk < 16; kk++) {
                float4 a0 = *(const float4*)&As[kk][tm];
                float4 a1 = *(const float4*)&As[kk][tm + 4];
                const ULL* bp = (const ULL*)&Bs[kk][teL];
                ULL b0 = bp[0], b1 = bp[1], b2 = bp[2], b3 = bp[3];
                float av[8] = {a0.x, a0.y, a0.z, a0.w, a1.x, a1.y, a1.z, a1.w};
                #pragma unroll
                for (int i = 0; i < 8; i++) {
                    ULL ap = bcast2(av[i]);
                    fma2(acc[i][0], ap, b0);
                    fma2(acc[i][1], ap, b1);
                    fma2(acc[i][2], ap, b2);
                    fma2(acc[i][3], ap, b3);
                }
            }
        }
        // fold this E-pass into the three running reductions (p stays in regs)
        const int te0 = e0 + teL;
        #pragma unroll
        for (int i = 0; i < 8; i++) {
            #pragma unroll
            for (int j = 0; j < 4; j++) {
                float2 p = unpk(acc[i][j]);
                const int ee = te0 + j * 2;
                float p0 = p.x + cbS[ee];
                float p1 = p.y + cbS[ee + 1];
                r1[i] += p0 + p1;
                r2[i]  = fmaf(p0, p0, fmaf(p1, p1, r2[i]));
                rd[i]  = fmaf(p0, uS[ee], fmaf(p1, uS[ee + 1], rd[i]));
            }
        }
    }

    // reduce over the 8 le-lanes sharing each token row
    #pragma unroll
    for (int i = 0; i < 8; i++) {
        #pragma unroll
        for (int off = 1; off < 8; off <<= 1) {
            r1[i] += __shfl_xor_sync(0xffffffffu, r1[i], off);
            r2[i] += __shfl_xor_sync(0xffffffffu, r2[i], off);
            rd[i] += __shfl_xor_sync(0xffffffffu, rd[i], off);
        }
    }
    __syncthreads();
    if (we == 1 && le == 0) {
        #pragma unroll
        for (int i = 0; i < 8; i++) {
            redS[0][tm + i] = r1[i]; redS[1][tm + i] = r2[i]; redS[2][tm + i] = rd[i];
        }
    }
    __syncthreads();
    if (we == 0 && le == 0) {
        const float S1 = g_cst[b * 2 + 0];
        const float K2 = g_cst[b * 2 + 1];
        #pragma unroll
        for (int i = 0; i < 8; i++) {
            float s1 = r1[i] + redS[0][tm + i];
            float s2 = r2[i] + redS[1][tm + i];
            float sd = rd[i] + redS[2][tm + i];
            float mu   = s1 * (1.0f / 768.0f);
            float var  = s2 * (1.0f / 768.0f) - mu * mu;
            float rstd = rsqrtf(var + 1e-5f);
            float score = 0.035355339059327376f * (rstd * (sd - mu * S1) + K2);
            g_scores[b * 1024 + m0 + tm + i] = score;
        }
    }
}

// ============================================================================
// Kernel 3: per-batch softmax over the 1024 non-cls scores -> output (B,1,32,32)
// ============================================================================
__global__ void softmax_kernel(float* __restrict__ out)
{
    __shared__ float red[8];
    const int b = blockIdx.x, tid = threadIdx.x;
    float4 s = *(const float4*)&g_scores[b * 1024 + tid * 4];

    float mx = fmaxf(fmaxf(s.x, s.y), fmaxf(s.z, s.w));
    #pragma unroll
    for (int off = 16; off; off >>= 1)
        mx = fmaxf(mx, __shfl_xor_sync(0xffffffffu, mx, off));
    if ((tid & 31) == 0) red[tid >> 5] = mx;
    __syncthreads();
    float m = red[0];
    #pragma unroll
    for (int i = 1; i < 8; i++) m = fmaxf(m, red[i]);

    float e0 = expf(s.x - m), e1 = expf(s.y - m);
    float e2 = expf(s.z - m), e3 = expf(s.w - m);
    float sum = e0 + e1 + e2 + e3;
    #pragma unroll
    for (int off = 16; off; off >>= 1)
        sum += __shfl_xor_sync(0xffffffffu, sum, off);
    __syncthreads();
    if ((tid & 31) == 0) red[tid >> 5] = sum;
    __syncthreads();
    float tot = 0.f;
    #pragma unroll
    for (int i = 0; i < 8; i++) tot += red[i];
    float inv = 1.0f / tot;

    float4 o = make_float4(e0 * inv, e1 * inv, e2 * inv, e3 * inv);
    *(float4*)&out[b * 1024 + tid * 4] = o;
}

// ============================================================================
extern "C" void kernel_launch(void* const* d_in, const int* in_sizes, int n_in,
                              void* d_out, int out_size)
{
    const float* x      = (const float*)d_in[0];  // (32,1024,32,32)
    const float* gender = (const float*)d_in[1];  // (32,32)
    const float* conv_w = (const float*)d_in[2];  // (768,1024)
    const float* conv_b = (const float*)d_in[3];  // (768)
    const float* ln_g   = (const float*)d_in[4];  // (768)
    const float* ln_b   = (const float*)d_in[5];  // (768)
    const float* cls    = (const float*)d_in[6];  // (1,1,768)
    const float* qkv_w  = (const float*)d_in[7];  // (2400,800)
    const float* qkv_b  = (const float*)d_in[8];  // (2400)

    prep_kernel<<<32, 256>>>(gender, cls, qkv_w, qkv_b, ln_g, ln_b);

    dim3 grid(8, 32);  // 8 token tiles x 32 batches
    fused_kernel<<<grid, 256>>>(x, conv_w, conv_b, ln_g);

    softmax_kernel<<<32, 256>>>((float*)d_out);
}

// round 6
// speedup vs baseline: 1.7205x; 1.7205x over previous
#include <cuda_runtime.h>
#include <math.h>

#define ULL unsigned long long

// ---------------- scratch (__device__ globals: no allocation allowed) --------
__device__ float g_qc0[800];            // bq + Wq[:, :768] @ cls
__device__ float g_M[33 * 800];         // row0 = W0, rows 1..32 = gender->w_eff map
__device__ float g_weff[32 * 800];      // per-batch effective key-projection vector
__device__ float g_cst[64];             // per-batch {S1, K2}
__device__ float g_part[32 * 6 * 3 * 1024]; // per (b, e-pass): {s1,s2,sd}[token]
__device__ int   g_counter;             // dynamic task counter

// ---------------- f32x2 packed-FMA helpers (sm_100+) ------------------------
__device__ __forceinline__ ULL bcast2(float a) {
    ULL r; asm("mov.b64 %0, {%1, %1};" : "=l"(r) : "f"(a)); return r;
}
__device__ __forceinline__ void fma2(ULL &d, ULL a, ULL b) {
    asm("fma.rn.f32x2 %0, %1, %2, %0;" : "+l"(d) : "l"(a), "l"(b));
}
__device__ __forceinline__ float2 unpk(ULL v) {
    float2 f; asm("mov.b64 {%0, %1}, %2;" : "=f"(f.x), "=f"(f.y) : "l"(v)); return f;
}

// ============================================================================
// prepA1: qc0[d] = bq[d] + Wq[d,:768].cls  (warp per row, coalesced)
//         + zero g_M, reset task counter.  grid 100 x 256.
// ============================================================================
__global__ void prepA1(const float* __restrict__ cls,
                       const float* __restrict__ qkv_w,
                       const float* __restrict__ qkv_b)
{
    const int tid = threadIdx.x;
    const int gtid = blockIdx.x * 256 + tid;
    for (int f = gtid; f < 33 * 800; f += 100 * 256) g_M[f] = 0.f;
    if (gtid == 0) g_counter = 0;

    const int d = blockIdx.x * 8 + (tid >> 5);
    const int lane = tid & 31;
    const float* wr = qkv_w + (size_t)d * 800;
    float acc = 0.f;
    for (int e = lane; e < 768; e += 32) acc = fmaf(wr[e], cls[e], acc);
    #pragma unroll
    for (int off = 16; off; off >>= 1)
        acc += __shfl_xor_sync(0xffffffffu, acc, off);
    if (lane == 0) g_qc0[d] = acc + qkv_b[d];
}

// ============================================================================
// prepA2: g_M[i][e] += sum_d u[d][i] * Wk[d][e]
//   u[d][0] = qc0[d], u[d][1+j] = Wq[d][768+j]
// grid (7 e-tiles of 128, 4 d-chunks of 200), 128 threads; REDG accumulate.
// ============================================================================
__global__ void prepA2(const float* __restrict__ qkv_w)
{
    __shared__ __align__(16) float us[200 * 36];
    const int tid = threadIdx.x;
    const int e = blockIdx.x * 128 + tid;
    const int d0 = blockIdx.y * 200;

    for (int f = tid; f < 200 * 36; f += 128) {
        int dd = f / 36, i = f - dd * 36;
        float v = 0.f;
        if (i == 0)       v = g_qc0[d0 + dd];
        else if (i < 33)  v = qkv_w[(size_t)(d0 + dd) * 800 + 768 + (i - 1)];
        us[f] = v;
    }
    __syncthreads();
    if (e >= 800) return;

    float4 a[9];
    #pragma unroll
    for (int q = 0; q < 9; q++) a[q] = make_float4(0.f, 0.f, 0.f, 0.f);

    const float* wkp = qkv_w + (size_t)(800 + d0) * 800 + e;
    #pragma unroll 2
    for (int dd = 0; dd < 200; dd++) {
        float wk = wkp[(size_t)dd * 800];
        const float4* up = (const float4*)&us[dd * 36];
        #pragma unroll
        for (int q = 0; q < 9; q++) {
            float4 u = up[q];
            a[q].x = fmaf(u.x, wk, a[q].x);
            a[q].y = fmaf(u.y, wk, a[q].y);
            a[q].z = fmaf(u.z, wk, a[q].z);
            a[q].w = fmaf(u.w, wk, a[q].w);
        }
    }
    #pragma unroll
    for (int q = 0; q < 9; q++) {
        float c[4] = {a[q].x, a[q].y, a[q].z, a[q].w};
        #pragma unroll
        for (int k = 0; k < 4; k++) {
            int i = q * 4 + k;
            if (i < 33) atomicAdd(&g_M[i * 800 + e], c[k]);
        }
    }
}

// ============================================================================
// prepB: per batch — w_eff = M[0] + g@M[1:], S1, K2 (= S2 + gdot + c0).
// ============================================================================
__global__ void prepB(const float* __restrict__ gender,
                      const float* __restrict__ qkv_w,
                      const float* __restrict__ qkv_b,
                      const float* __restrict__ ln_g,
                      const float* __restrict__ ln_b)
{
    __shared__ float gs[32];
    __shared__ float red[24];
    const int b = blockIdx.x, tid = threadIdx.x;
    if (tid < 32) gs[tid] = gender[b * 32 + tid];
    __syncthreads();

    float ps1 = 0.f, ps2 = 0.f, pex = 0.f;
    for (int e = tid; e < 800; e += 256) {
        float wf = g_M[e];
        #pragma unroll
        for (int j = 0; j < 32; j++) wf = fmaf(gs[j], g_M[(1 + j) * 800 + e], wf);
        g_weff[b * 800 + e] = wf;
        if (e < 768) { ps1 = fmaf(ln_g[e], wf, ps1); ps2 = fmaf(ln_b[e], wf, ps2); }
        else         { pex = fmaf(gs[e - 768], wf, pex); }
    }
    // c0 = q_cls . bk, with q_cls[d] = qc0[d] + Wq[d,768:].g
    for (int d = tid; d < 800; d += 256) {
        float qd = g_qc0[d];
        const float* wq = qkv_w + (size_t)d * 800 + 768;
        #pragma unroll
        for (int j = 0; j < 32; j++) qd = fmaf(wq[j], gs[j], qd);
        pex = fmaf(qd, qkv_b[800 + d], pex);
    }
    #pragma unroll
    for (int off = 16; off; off >>= 1) {
        ps1 += __shfl_xor_sync(0xffffffffu, ps1, off);
        ps2 += __shfl_xor_sync(0xffffffffu, ps2, off);
        pex += __shfl_xor_sync(0xffffffffu, pex, off);
    }
    const int w = tid >> 5;
    if ((tid & 31) == 0) { red[w] = ps1; red[8 + w] = ps2; red[16 + w] = pex; }
    __syncthreads();
    if (tid == 0) {
        float S1 = 0.f, S2 = 0.f, EX = 0.f;
        for (int i = 0; i < 8; i++) { S1 += red[i]; S2 += red[8 + i]; EX += red[16 + i]; }
        g_cst[b * 2 + 0] = S1;
        g_cst[b * 2 + 1] = S2 + EX;
    }
}

// ============================================================================
// fused: persistent dynamic tasks. Task = (b, m-tile of 128, e-pass of 128).
// Double-buffered smem GEMM (1 barrier per k-chunk), LDG latency hidden.
// Writes per-pass partial reductions (s1, s2, sd) to g_part.
// ============================================================================
__global__ __launch_bounds__(256)
void fused_kernel(const float* __restrict__ x,
                  const float* __restrict__ W,
                  const float* __restrict__ conv_b,
                  const float* __restrict__ ln_g)
{
    __shared__ __align__(16) float As[2][16][128];
    __shared__ __align__(16) float Bs[2][16][132];
    __shared__ float uS[128];
    __shared__ float cbS[128];
    __shared__ float redS[3][128];
    __shared__ int s_task;

    const int tid = threadIdx.x;
    const int w = tid >> 5, lane = tid & 31;
    const int wm = w & 3, we = w >> 2;
    const int lm = lane >> 3, le = lane & 7;
    const int tm  = wm * 32 + lm * 8;
    const int teL = we * 64 + le * 8;
    const int rA = tid >> 5, cA = (tid & 31) * 4;   // A-load coords
    const int eB = tid >> 2, qq = (tid & 3) * 4;    // B-load coords

    while (true) {
        if (tid == 0) s_task = atomicAdd(&g_counter, 1);
        __syncthreads();
        const int task = s_task;
        if (task >= 1536) return;

        const int b  = task / 48;
        const int r_ = task - b * 48;
        const int mt = r_ / 6;
        const int ep = r_ - mt * 6;
        const int m0 = mt * 128;
        const int E0 = ep * 128;

        if (tid < 128) {
            uS[tid]  = ln_g[E0 + tid] * g_weff[b * 800 + E0 + tid];
            cbS[tid] = conv_b[E0 + tid];
        }

        const float* xb = x + (size_t)b * (1024 * 1024) + m0;
        const float* Wb = W + (size_t)E0 * 1024;

        float4 ra0, ra1, rb0, rb1;
        // prologue: chunk 0 -> buf 0
        ra0 = *(const float4*)(xb + (size_t)rA * 1024 + cA);
        ra1 = *(const float4*)(xb + (size_t)(rA + 8) * 1024 + cA);
        rb0 = *(const float4*)(Wb + (size_t)eB * 1024 + qq);
        rb1 = *(const float4*)(Wb + (size_t)(eB + 64) * 1024 + qq);
        *(float4*)&As[0][rA][cA] = ra0;
        *(float4*)&As[0][rA + 8][cA] = ra1;
        Bs[0][qq + 0][eB] = rb0.x; Bs[0][qq + 1][eB] = rb0.y;
        Bs[0][qq + 2][eB] = rb0.z; Bs[0][qq + 3][eB] = rb0.w;
        Bs[0][qq + 0][eB + 64] = rb1.x; Bs[0][qq + 1][eB + 64] = rb1.y;
        Bs[0][qq + 2][eB + 64] = rb1.z; Bs[0][qq + 3][eB + 64] = rb1.w;
        __syncthreads();

        ULL acc[8][4];
        #pragma unroll
        for (int i = 0; i < 8; i++)
            #pragma unroll
            for (int j = 0; j < 4; j++) acc[i][j] = 0ull;

        for (int kc = 0; kc < 64; kc++) {
            const int cur = kc & 1;
            if (kc < 63) {
                const int c0 = (kc + 1) * 16;
                ra0 = *(const float4*)(xb + (size_t)(c0 + rA) * 1024 + cA);
                ra1 = *(const float4*)(xb + (size_t)(c0 + rA + 8) * 1024 + cA);
                rb0 = *(const float4*)(Wb + (size_t)eB * 1024 + c0 + qq);
                rb1 = *(const float4*)(Wb + (size_t)(eB + 64) * 1024 + c0 + qq);
            }
            const float* Asb = &As[cur][0][0];
            const float* Bsb = &Bs[cur][0][0];
            #pragma unroll
            for (int kk = 0; kk < 16; kk++) {
                float4 a0 = *(const float4*)(Asb + kk * 128 + tm);
                float4 a1 = *(const float4*)(Asb + kk * 128 + tm + 4);
                const ULL* bp = (const ULL*)(Bsb + kk * 132 + teL);
                ULL b0 = bp[0], b1 = bp[1], b2 = bp[2], b3 = bp[3];
                float av[8] = {a0.x, a0.y, a0.z, a0.w, a1.x, a1.y, a1.z, a1.w};
                #pragma unroll
                for (int i = 0; i < 8; i++) {
                    ULL ap = bcast2(av[i]);
                    fma2(acc[i][0], ap, b0);
                    fma2(acc[i][1], ap, b1);
                    fma2(acc[i][2], ap, b2);
                    fma2(acc[i][3], ap, b3);
                }
            }
            if (kc < 63) {
                const int nx = cur ^ 1;
                *(float4*)&As[nx][rA][cA] = ra0;
                *(float4*)&As[nx][rA + 8][cA] = ra1;
                Bs[nx][qq + 0][eB] = rb0.x; Bs[nx][qq + 1][eB] = rb0.y;
                Bs[nx][qq + 2][eB] = rb0.z; Bs[nx][qq + 3][eB] = rb0.w;
                Bs[nx][qq + 0][eB + 64] = rb1.x; Bs[nx][qq + 1][eB + 64] = rb1.y;
                Bs[nx][qq + 2][eB + 64] = rb1.z; Bs[nx][qq + 3][eB + 64] = rb1.w;
                __syncthreads();
            }
        }

        // fold this e-pass into (s1, s2, sd)
        float r1[8], r2[8], rd[8];
        #pragma unroll
        for (int i = 0; i < 8; i++) { r1[i] = 0.f; r2[i] = 0.f; rd[i] = 0.f; }
        #pragma unroll
        for (int i = 0; i < 8; i++) {
            #pragma unroll
            for (int j = 0; j < 4; j++) {
                float2 p = unpk(acc[i][j]);
                const int ee = teL + j * 2;
                float p0 = p.x + cbS[ee];
                float p1 = p.y + cbS[ee + 1];
                r1[i] += p0 + p1;
                r2[i]  = fmaf(p0, p0, fmaf(p1, p1, r2[i]));
                rd[i]  = fmaf(p0, uS[ee], fmaf(p1, uS[ee + 1], rd[i]));
            }
        }
        #pragma unroll
        for (int i = 0; i < 8; i++) {
            #pragma unroll
            for (int off = 1; off < 8; off <<= 1) {
                r1[i] += __shfl_xor_sync(0xffffffffu, r1[i], off);
                r2[i] += __shfl_xor_sync(0xffffffffu, r2[i], off);
                rd[i] += __shfl_xor_sync(0xffffffffu, rd[i], off);
            }
        }
        __syncthreads();
        if (we == 1 && le == 0) {
            #pragma unroll
            for (int i = 0; i < 8; i++) {
                redS[0][tm + i] = r1[i]; redS[1][tm + i] = r2[i]; redS[2][tm + i] = rd[i];
            }
        }
        __syncthreads();
        if (we == 0 && le == 0) {
            const int base = ((b * 6 + ep) * 3) * 1024 + m0 + tm;
            #pragma unroll
            for (int i = 0; i < 8; i++) {
                g_part[base + i]        = r1[i] + redS[0][tm + i];
                g_part[base + 1024 + i] = r2[i] + redS[1][tm + i];
                g_part[base + 2048 + i] = rd[i] + redS[2][tm + i];
            }
        }
    }
}

// ============================================================================
// final: combine e-pass partials -> score -> softmax -> out (B,1,32,32)
// ============================================================================
__global__ void final_kernel(float* __restrict__ out)
{
    __shared__ float sc[1024];
    __shared__ float red[8];
    const int b = blockIdx.x, tid = threadIdx.x;
    const float S1 = g_cst[b * 2 + 0];
    const float K2 = g_cst[b * 2 + 1];

    #pragma unroll
    for (int k = 0; k < 4; k++) {
        const int tk = tid + k * 256;
        float s1 = 0.f, s2 = 0.f, sd = 0.f;
        #pragma unroll
        for (int ep = 0; ep < 6; ep++) {
            const int base = ((b * 6 + ep) * 3) * 1024 + tk;
            s1 += g_part[base];
            s2 += g_part[base + 1024];
            sd += g_part[base + 2048];
        }
        float mu   = s1 * (1.0f / 768.0f);
        float var  = s2 * (1.0f / 768.0f) - mu * mu;
        float rstd = rsqrtf(var + 1e-5f);
        sc[tk] = 0.035355339059327376f * (rstd * (sd - mu * S1) + K2);
    }
    __syncthreads();

    float4 s = *(const float4*)&sc[tid * 4];
    float mx = fmaxf(fmaxf(s.x, s.y), fmaxf(s.z, s.w));
    #pragma unroll
    for (int off = 16; off; off >>= 1)
        mx = fmaxf(mx, __shfl_xor_sync(0xffffffffu, mx, off));
    if ((tid & 31) == 0) red[tid >> 5] = mx;
    __syncthreads();
    float m = red[0];
    #pragma unroll
    for (int i = 1; i < 8; i++) m = fmaxf(m, red[i]);

    float e0 = expf(s.x - m), e1 = expf(s.y - m);
    float e2 = expf(s.z - m), e3 = expf(s.w - m);
    float sum = e0 + e1 + e2 + e3;
    #pragma unroll
    for (int off = 16; off; off >>= 1)
        sum += __shfl_xor_sync(0xffffffffu, sum, off);
    __syncthreads();
    if ((tid & 31) == 0) red[tid >> 5] = sum;
    __syncthreads();
    float tot = 0.f;
    #pragma unroll
    for (int i = 0; i < 8; i++) tot += red[i];
    float inv = 1.0f / tot;

    float4 o = make_float4(e0 * inv, e1 * inv, e2 * inv, e3 * inv);
    *(float4*)&out[b * 1024 + tid * 4] = o;
}

// ============================================================================
extern "C" void kernel_launch(void* const* d_in, const int* in_sizes, int n_in,
                              void* d_out, int out_size)
{
    const float* x      = (const float*)d_in[0];  // (32,1024,32,32)
    const float* gender = (const float*)d_in[1];  // (32,32)
    const float* conv_w = (const float*)d_in[2];  // (768,1024)
    const float* conv_b = (const float*)d_in[3];  // (768)
    const float* ln_g   = (const float*)d_in[4];  // (768)
    const float* ln_b   = (const float*)d_in[5];  // (768)
    const float* cls    = (const float*)d_in[6];  // (1,1,768)
    const float* qkv_w  = (const float*)d_in[7];  // (2400,800)
    const float* qkv_b  = (const float*)d_in[8];  // (2400)

    prepA1<<<100, 256>>>(cls, qkv_w, qkv_b);
    prepA2<<<dim3(7, 4), 128>>>(qkv_w);
    prepB<<<32, 256>>>(gender, qkv_w, qkv_b, ln_g, ln_b);

    fused_kernel<<<304, 256>>>(x, conv_w, conv_b, ln_g);

    final_kernel<<<32, 256>>>((float*)d_out);
}